// round 10
// baseline (speedup 1.0000x reference)
#include <cuda_runtime.h>
#include <cuda_bf16.h>
#include <mma.h>
#include <math.h>
#include <stdint.h>

using namespace nvcuda;

#define BATCH 16
#define HH 256
#define WW 256
#define HW (HH*WW)
#define HID 64
#define C_NN 4
#define C_CO 4
#define FT_C 2
#define CIN0 6          /* C_NN + FT_C */
#define NTAP0 (CIN0*9)  /* 54 */
#define OUTC (C_CO*4)   /* 16 */

typedef unsigned long long ull;

// ---------------------------------------------------------------------------
// Packed f32x2 helpers
// ---------------------------------------------------------------------------
__device__ __forceinline__ ull ffma2(ull a, ull b, ull c) {
    ull d;
    asm("fma.rn.f32x2 %0, %1, %2, %3;" : "=l"(d) : "l"(a), "l"(b), "l"(c));
    return d;
}
__device__ __forceinline__ ull pack2(float lo, float hi) {
    ull d;
    asm("mov.b64 %0, {%1, %2};" : "=l"(d)
        : "r"(__float_as_uint(lo)), "r"(__float_as_uint(hi)));
    return d;
}
__device__ __forceinline__ void unpack2(ull v, float& lo, float& hi) {
    unsigned int a, b;
    asm("mov.b64 {%0, %1}, %2;" : "=r"(a), "=r"(b) : "l"(v));
    lo = __uint_as_float(a); hi = __uint_as_float(b);
}

// bf16x2 pack: result word = [f1 | f0] (f0 in low half)
__device__ __forceinline__ uint32_t bf16x2_rn(float f0, float f1) {
    uint32_t r;
    asm("cvt.rn.bf16x2.f32 %0, %1, %2;" : "=r"(r) : "f"(f1), "f"(f0));
    return r;
}
// split (f0,f1) into hi/lo bf16x2 words and store at byte offset `off`
__device__ __forceinline__ void split_sts(char* Ahi, char* Alo, uint32_t off,
                                          float f0, float f1) {
    uint32_t hi2 = bf16x2_rn(f0, f1);
    float h0 = __uint_as_float(hi2 << 16);
    float h1 = __uint_as_float(hi2 & 0xFFFF0000u);
    uint32_t lo2 = bf16x2_rn(f0 - h0, f1 - h1);
    *(uint32_t*)(Ahi + off) = hi2;
    *(uint32_t*)(Alo + off) = lo2;
}

// ---------------------------------------------------------------------------
// Scratch
// ---------------------------------------------------------------------------
__device__ float g_hidden[(size_t)BATCH * HID * HW];
__device__ __align__(16) float g_w0t[NTAP0 * HID];          // conv0 W [tap][o]
__device__ __align__(16) __nv_bfloat16 g_wbh[4 * HID * HID]; // [l][k][n] hi
__device__ __align__(16) __nv_bfloat16 g_wbl[4 * HID * HID]; // [l][k][n] lo

// ---------------------------------------------------------------------------
// Prep: conv0 transpose + bf16 hi/lo split of 1x1 weights into [k][n] layout
// ---------------------------------------------------------------------------
__global__ void kprep(const float* __restrict__ w0,
                      const float* __restrict__ w1, const float* __restrict__ w2,
                      const float* __restrict__ w3, const float* __restrict__ w4)
{
    const int i = blockIdx.x * 256 + threadIdx.x;
    if (i < NTAP0 * HID) {
        const int tap = i >> 6;
        const int o   = i & 63;
        g_w0t[tap * HID + o] = w0[o * NTAP0 + tap];
    }
    if (i < 4 * HID * HID) {
        const int l   = i >> 12;
        const int rem = i & 4095;
        const int k   = rem >> 6;    // input channel
        const int n   = rem & 63;    // output channel
        const float* w = (l == 0) ? w1 : (l == 1) ? w2 : (l == 2) ? w3 : w4;
        const float v = w[n * HID + k];
        const __nv_bfloat16 hv = __float2bfloat16(v);
        const float lo = v - __bfloat162float(hv);
        g_wbh[i] = hv;
        g_wbl[i] = __float2bfloat16(lo);
    }
}

// ---------------------------------------------------------------------------
// Kernel A: conv0 (fp32 FFMA2) + 4x (1x1 64->64) via WMMA bf16 3-term split.
// Block = 256 threads (8 warps) = one 128-px tile. Warp w owns px rows
// 16w..16w+15 end-to-end through all 4 MMA layers (no cross-warp deps).
// ---------------------------------------------------------------------------
#define ALD 72                      /* A-tile ld, bf16 elements (144 B/row) */
#define SLD 68                      /* scratch ld, floats (272 B/row)      */
#define SM_AHI   0
#define SM_ALO   (128 * ALD * 2)                 /* 18432 */
#define SM_SCR   (SM_ALO + 128 * ALD * 2)        /* 36864 */
#define SM_BIAS  (SM_SCR + 128 * SLD * 4)        /* 71680 */
#define SM_TOTAL (SM_BIAS + 4 * HID * 4)         /* 72704 */

extern __shared__ char smemT[];

__global__ void __launch_bounds__(256, 3) knet_mma(
    const float* __restrict__ input, const float* __restrict__ ft,
    const float* __restrict__ b0, const float* __restrict__ b1,
    const float* __restrict__ b2, const float* __restrict__ b3,
    const float* __restrict__ b4)
{
    char* AhiB = smemT + SM_AHI;
    char* AloB = smemT + SM_ALO;
    float* scr   = (float*)(smemT + SM_SCR);
    float* sbias = (float*)(smemT + SM_BIAS);

    const int t = threadIdx.x;
    if (t < 64) {
        sbias[t]       = b1[t];
        sbias[64 + t]  = b2[t];
        sbias[128 + t] = b3[t];
        sbias[192 + t] = b4[t];
    }

    const int xs = blockIdx.x;   // 0/1 x-half
    const int y  = blockIdx.y;
    const int b  = blockIdx.z;
    const int xbase = xs * 128;

    // ---- conv0: thread = 8 channels (jg) x 4 pixels (pg + 32m) ----
    {
        const int jg = t >> 5;
        const int pg = t & 31;
        ull acc[4][4];
        {
            const float* bp = b0 + jg * 8;
#pragma unroll
            for (int p = 0; p < 4; p++) {
                const ull bv = pack2(bp[2 * p], bp[2 * p + 1]);
#pragma unroll
                for (int m = 0; m < 4; m++) acc[p][m] = bv;
            }
        }
        const float* zb = input + (size_t)b * 8 * HW;
        const float* fb = ft    + (size_t)b * FT_C * HW;
#pragma unroll
        for (int ci = 0; ci < CIN0; ci++) {
            const float* src = (ci < C_NN) ? (zb + ci * HW) : (fb + (ci - C_NN) * HW);
#pragma unroll
            for (int ky = 0; ky < 3; ky++) {
                const int yy = y + ky - 1;
                const bool yv = (unsigned)yy < HH;
                const float* rowp = src + yy * WW;
                float v[4][3];
#pragma unroll
                for (int m = 0; m < 4; m++) {
                    const int x = xbase + pg + 32 * m;
                    v[m][0] = (yv && x > 0)      ? __ldg(rowp + x - 1) : 0.f;
                    v[m][1] = yv                 ? __ldg(rowp + x)     : 0.f;
                    v[m][2] = (yv && x < WW - 1) ? __ldg(rowp + x + 1) : 0.f;
                }
#pragma unroll
                for (int kx = 0; kx < 3; kx++) {
                    const ulonglong2* wr = (const ulonglong2*)
                        (g_w0t + (ci * 9 + ky * 3 + kx) * HID + jg * 8);
                    ulonglong2 w0v = wr[0], w1v = wr[1];
#pragma unroll
                    for (int m = 0; m < 4; m++) {
                        const ull td = pack2(v[m][kx], v[m][kx]);
                        acc[0][m] = ffma2(w0v.x, td, acc[0][m]);
                        acc[1][m] = ffma2(w0v.y, td, acc[1][m]);
                        acc[2][m] = ffma2(w1v.x, td, acc[2][m]);
                        acc[3][m] = ffma2(w1v.y, td, acc[3][m]);
                    }
                }
            }
        }
        // relu + bf16-split store into A tiles [px][ch], ld=72
#pragma unroll
        for (int m = 0; m < 4; m++) {
            const int px = pg + 32 * m;
#pragma unroll
            for (int p = 0; p < 4; p++) {
                const int ch = jg * 8 + 2 * p;
                float f0, f1; unpack2(acc[p][m], f0, f1);
                split_sts(AhiB, AloB, (uint32_t)(px * (ALD * 2) + ch * 2),
                          fmaxf(f0, 0.f), fmaxf(f1, 0.f));
            }
        }
    }
    __syncthreads();

    // ---- 4 WMMA layers, fully warp-local ----
    const int w    = t >> 5;
    const int lane = t & 31;
    const __nv_bfloat16* Ahi = (const __nv_bfloat16*)AhiB;
    const __nv_bfloat16* Alo = (const __nv_bfloat16*)AloB;
    float* myscr = scr + (16 * w) * SLD;

#pragma unroll 1
    for (int l = 0; l < 4; l++) {
        wmma::fragment<wmma::accumulator, 16, 16, 16, float> accf[4];
#pragma unroll
        for (int n = 0; n < 4; n++) wmma::fill_fragment(accf[n], 0.f);

#pragma unroll
        for (int k = 0; k < 4; k++) {
            wmma::fragment<wmma::matrix_a, 16, 16, 16, __nv_bfloat16, wmma::row_major> ah, al;
            wmma::load_matrix_sync(ah, Ahi + (16 * w) * ALD + 16 * k, ALD);
            wmma::load_matrix_sync(al, Alo + (16 * w) * ALD + 16 * k, ALD);
#pragma unroll
            for (int n = 0; n < 4; n++) {
                wmma::fragment<wmma::matrix_b, 16, 16, 16, __nv_bfloat16, wmma::row_major> bh, bl;
                wmma::load_matrix_sync(bh, g_wbh + l * 4096 + (16 * k) * HID + 16 * n, HID);
                wmma::mma_sync(accf[n], ah, bh, accf[n]);
                wmma::mma_sync(accf[n], al, bh, accf[n]);
                wmma::load_matrix_sync(bl, g_wbl + l * 4096 + (16 * k) * HID + 16 * n, HID);
                wmma::mma_sync(accf[n], ah, bl, accf[n]);
            }
        }
#pragma unroll
        for (int n = 0; n < 4; n++)
            wmma::store_matrix_sync(myscr + 16 * n, accf[n], SLD, wmma::mem_row_major);
        __syncwarp();   // store_matrix_sync lanes' writes visible to all lanes

        if (l < 3) {
            // warp-local epilogue: bias + relu + re-split into own A rows
            const int px = t >> 1;           // px in [16w, 16w+15]
            const int h  = t & 1;
            const float* srow = scr + px * SLD;
#pragma unroll
            for (int i = 0; i < 16; i++) {
                const int ch = h * 32 + 2 * i;
                float2 v = *(const float2*)(srow + ch);
                const float f0 = fmaxf(v.x + sbias[l * 64 + ch],     0.f);
                const float f1 = fmaxf(v.y + sbias[l * 64 + ch + 1], 0.f);
                split_sts(AhiB, AloB, (uint32_t)(px * (ALD * 2) + ch * 2), f0, f1);
            }
            __syncwarp();   // re-split stores visible before next load_matrix_sync
        }
    }

    // ---- final: bias + relu + coalesced write to g_hidden ----
    __syncthreads();
    const size_t gb = ((size_t)b * HID) * HW + (size_t)y * WW + xbase;
#pragma unroll
    for (int cc = 0; cc < 8; cc++) {
        const int ch = w * 8 + cc;
        const float bias = sbias[192 + ch];
#pragma unroll
        for (int blk = 0; blk < 4; blk++) {
            const int px = blk * 32 + lane;
            const float v = fmaxf(scr[px * SLD + ch] + bias, 0.f);
            g_hidden[gb + (size_t)ch * HW + px] = v;
        }
    }
}

// ---------------------------------------------------------------------------
// Kernel B: convz(3x3, 64->16) + spline (round-5 passing version, unchanged)
// ---------------------------------------------------------------------------
__global__ void __launch_bounds__(256, 2) kspline(
    const float* __restrict__ input,
    const float* __restrict__ wz, const float* __restrict__ bz,
    const float* __restrict__ logs,
    float* __restrict__ out)
{
    __shared__ __align__(16) float swz[HID * 9 * OUTC];
    __shared__ float sbz[OUTC];
    __shared__ float sscale[OUTC];
    __shared__ float sred[8];

    const int t = threadIdx.x;
    for (int i = t; i < HID * 9 * OUTC; i += 256) {
        const int o  = i & 15;
        const int ct = i >> 4;
        swz[i] = wz[o * (HID * 9) + ct];
    }
    if (t < OUTC) {
        sbz[t]    = bz[t];
        sscale[t] = expf(3.f * logs[t]);
    }
    __syncthreads();

    const int warp = t >> 5;
    const int lane = t & 31;
    const int b  = blockIdx.z;
    const int y  = blockIdx.y * 4 + (warp >> 1);
    const int xh = warp & 1;
    const int x0 = xh * 128 + lane * 4;

    ull accp[4][8];
#pragma unroll
    for (int j = 0; j < 4; j++)
#pragma unroll
        for (int p = 0; p < 8; p++) accp[j][p] = 0ull;

    const float* hb = g_hidden + (size_t)b * HID * HW;

#pragma unroll 1
    for (int c = 0; c < HID; c++) {
        const float* hp = hb + (size_t)c * HW;
        float e[3][6];
#pragma unroll
        for (int r = 0; r < 3; r++) {
            const int yy = y + r - 1;
            const bool yv = (unsigned)yy < HH;
            float4 v;
            if (yv) v = *(const float4*)(hp + yy * WW + x0);
            else    v = make_float4(0.f, 0.f, 0.f, 0.f);
            float lft = __shfl_up_sync(0xffffffffu, v.w, 1);
            float rgt = __shfl_down_sync(0xffffffffu, v.x, 1);
            if (lane == 0)  lft = (yv && x0 > 0)      ? __ldg(hp + yy * WW + x0 - 1) : 0.f;
            if (lane == 31) rgt = (yv && x0 + 4 < WW) ? __ldg(hp + yy * WW + x0 + 4) : 0.f;
            e[r][0] = lft; e[r][1] = v.x; e[r][2] = v.y;
            e[r][3] = v.z; e[r][4] = v.w; e[r][5] = rgt;
        }
#pragma unroll
        for (int r = 0; r < 3; r++) {
#pragma unroll
            for (int kx = 0; kx < 3; kx++) {
                const int tt = r * 3 + kx;
                const ulonglong2* wt =
                    (const ulonglong2*)(swz + (c * 9 + tt) * OUTC);
                ulonglong2 wv0 = wt[0], wv1 = wt[1];
                ulonglong2 wv2 = wt[2], wv3 = wt[3];
#pragma unroll
                for (int j = 0; j < 4; j++) {
                    const float ev = e[r][j + kx];
                    const ull d = pack2(ev, ev);
                    accp[j][0] = ffma2(wv0.x, d, accp[j][0]);
                    accp[j][1] = ffma2(wv0.y, d, accp[j][1]);
                    accp[j][2] = ffma2(wv1.x, d, accp[j][2]);
                    accp[j][3] = ffma2(wv1.y, d, accp[j][3]);
                    accp[j][4] = ffma2(wv2.x, d, accp[j][4]);
                    accp[j][5] = ffma2(wv2.y, d, accp[j][5]);
                    accp[j][6] = ffma2(wv3.x, d, accp[j][6]);
                    accp[j][7] = ffma2(wv3.y, d, accp[j][7]);
                }
            }
        }
    }

    const float* xin = input + (size_t)b * 8 * HW + (size_t)y * WW + x0;
    float*       oo  = out   + (size_t)b * 8 * HW + (size_t)y * WW + x0;
    float ladsum = 0.f;

#pragma unroll
    for (int co = 0; co < C_CO; co++) {
        *(float4*)(oo + (size_t)co * HW) = *(const float4*)(xin + (size_t)co * HW);

        float4 x2v = *(const float4*)(xin + (size_t)(4 + co) * HW);
        const float x2a[4] = { x2v.x, x2v.y, x2v.z, x2v.w };
        float rs[4];
#pragma unroll
        for (int j = 0; j < 4; j++) {
            float rw, rh, rd, sh;
            unpack2(accp[j][2 * co],     rw, rh);
            unpack2(accp[j][2 * co + 1], rd, sh);
            rw = (rw + sbz[co * 4 + 0]) * sscale[co * 4 + 0];
            rh = (rh + sbz[co * 4 + 1]) * sscale[co * 4 + 1];
            rd = (rd + sbz[co * 4 + 2]) * sscale[co * 4 + 2];
            sh = (sh + sbz[co * 4 + 3]) * sscale[co * 4 + 3];

            const float x2 = x2a[j];
            const bool inside = (x2 > -0.5f) && (x2 < 0.5f);
            const float xs2 = inside ? x2 : 0.f;

            const float width = 1.f / (1.f + expf(-rw)) * 0.998f + 0.001f;
            const float hh2   = 1.f / (1.f + expf(-rh)) * 0.998f + 0.001f;
            const float dd    = expf(rd) * 0.999f + 0.001f;

            const float cw1 = width - 0.5f;
            const float ch1 = hh2   - 0.5f;
            const bool bin1 = xs2 >= cw1;

            const float in_cw = bin1 ? cw1 : -0.5f;
            const float in_w  = bin1 ? (0.5f - cw1) : (cw1 + 0.5f);
            const float in_ch = bin1 ? ch1 : -0.5f;
            const float in_h  = bin1 ? (0.5f - ch1) : (ch1 + 0.5f);
            const float d0    = bin1 ? dd : 1.f;
            const float d1    = bin1 ? 1.f : dd;

            const float delta = in_h / in_w;
            const float theta = (xs2 - in_cw) / in_w;
            const float omt   = 1.f - theta;
            const float t1mt  = theta * omt;
            const float denom = delta + (d0 + d1 - 2.f * delta) * t1mt;
            float outv = in_ch + in_h * (delta * theta * theta + d0 * t1mt) / denom;
            const float dnum = delta * delta *
                (d1 * theta * theta + 2.f * delta * t1mt + d0 * omt * omt);
            const float lad  = logf(dnum) - 2.f * logf(denom);
            outv = fminf(fmaxf(outv, -0.5f), 0.5f);

            rs[j] = (inside ? outv : x2) + sh;
            ladsum += inside ? lad : 0.f;
        }
        *(float4*)(oo + (size_t)(4 + co) * HW) = make_float4(rs[0], rs[1], rs[2], rs[3]);
    }

#pragma unroll
    for (int off = 16; off; off >>= 1)
        ladsum += __shfl_down_sync(0xffffffffu, ladsum, off);
    if (lane == 0) sred[warp] = ladsum;
    __syncthreads();
    if (t < 8) {
        float v = sred[t];
#pragma unroll
        for (int off = 4; off; off >>= 1)
            v += __shfl_down_sync(0xffu, v, off);
        if (t == 0) atomicAdd(out + (size_t)BATCH * 8 * HW + b, v);
    }
}

// Seed the logdet outputs from the input logdet (d_out is poisoned).
__global__ void kinit(const float* __restrict__ logdet, float* __restrict__ out)
{
    const int t = threadIdx.x;
    if (t < BATCH) out[(size_t)BATCH * 8 * HW + t] = logdet[t];
}

// ---------------------------------------------------------------------------
extern "C" void kernel_launch(void* const* d_in, const int* in_sizes, int n_in,
                              void* d_out, int out_size)
{
    const float* input  = (const float*)d_in[0];
    const float* logdet = (const float*)d_in[1];
    const float* ft     = (const float*)d_in[2];
    const float* w0     = (const float*)d_in[3];
    const float* b0     = (const float*)d_in[4];
    const float* w1     = (const float*)d_in[5];
    const float* b1     = (const float*)d_in[6];
    const float* w2     = (const float*)d_in[7];
    const float* b2     = (const float*)d_in[8];
    const float* w3     = (const float*)d_in[9];
    const float* b3     = (const float*)d_in[10];
    const float* w4     = (const float*)d_in[11];
    const float* b4     = (const float*)d_in[12];
    const float* wz     = (const float*)d_in[13];
    const float* bz     = (const float*)d_in[14];
    const float* logs   = (const float*)d_in[15];
    float* out = (float*)d_out;

    cudaFuncSetAttribute(knet_mma, cudaFuncAttributeMaxDynamicSharedMemorySize, SM_TOTAL);

    kinit<<<1, 32>>>(logdet, out);
    kprep<<<64, 256>>>(w0, w1, w2, w3, w4);

    dim3 gA(2, 256, 16);
    knet_mma<<<gA, 256, SM_TOTAL>>>(input, ft, b0, b1, b2, b3, b4);

    dim3 gB(1, 64, 16);
    kspline<<<gB, 256>>>(input, wz, bz, logs, out);
}

// round 11
// speedup vs baseline: 1.9930x; 1.9930x over previous
#include <cuda_runtime.h>
#include <cuda_bf16.h>
#include <math.h>
#include <stdint.h>

#define BATCH 16
#define HH 256
#define WW 256
#define HW (HH*WW)
#define HID 64
#define C_NN 4
#define C_CO 4
#define FT_C 2
#define CIN0 6          /* C_NN + FT_C */
#define NTAP0 (CIN0*9)  /* 54 */
#define OUTC (C_CO*4)   /* 16 */

typedef unsigned long long ull;

// ---------------------------------------------------------------------------
// Packed f32x2 helpers
// ---------------------------------------------------------------------------
__device__ __forceinline__ ull ffma2(ull a, ull b, ull c) {
    ull d;
    asm("fma.rn.f32x2 %0, %1, %2, %3;" : "=l"(d) : "l"(a), "l"(b), "l"(c));
    return d;
}
__device__ __forceinline__ ull pack2(float lo, float hi) {
    ull d;
    asm("mov.b64 %0, {%1, %2};" : "=l"(d)
        : "r"(__float_as_uint(lo)), "r"(__float_as_uint(hi)));
    return d;
}
__device__ __forceinline__ void unpack2(ull v, float& lo, float& hi) {
    unsigned int a, b;
    asm("mov.b64 {%0, %1}, %2;" : "=r"(a), "=r"(b) : "l"(v));
    lo = __uint_as_float(a); hi = __uint_as_float(b);
}
// bf16x2 pack: f0 -> LOW half, f1 -> HIGH half
__device__ __forceinline__ uint32_t bf16x2_rn(float f0, float f1) {
    uint32_t r;
    asm("cvt.rn.bf16x2.f32 %0, %1, %2;" : "=r"(r) : "f"(f1), "f"(f0));
    return r;
}
// split (f0,f1) into hi/lo bf16x2 register words
__device__ __forceinline__ void split_pair(uint32_t& hi, uint32_t& lo,
                                           float f0, float f1) {
    hi = bf16x2_rn(f0, f1);
    float h0f = __uint_as_float(hi << 16);
    float h1f = __uint_as_float(hi & 0xFFFF0000u);
    lo = bf16x2_rn(f0 - h0f, f1 - h1f);
}

// mma.m16n8k16 row.col f32.bf16.bf16.f32, D += A*B
#define MMA_16816(D, A, BX, BY)                                              \
    asm volatile("mma.sync.aligned.m16n8k16.row.col.f32.bf16.bf16.f32 "      \
        "{%0,%1,%2,%3},{%4,%5,%6,%7},{%8,%9},{%0,%1,%2,%3};"                 \
        : "+f"((D)[0]), "+f"((D)[1]), "+f"((D)[2]), "+f"((D)[3])             \
        : "r"((A)[0]), "r"((A)[1]), "r"((A)[2]), "r"((A)[3]),                \
          "r"(BX), "r"(BY))

// ---------------------------------------------------------------------------
// Scratch
// ---------------------------------------------------------------------------
__device__ float g_hidden[(size_t)BATCH * HID * HW];
__device__ __align__(16) float g_w0t[NTAP0 * HID];       // conv0 W [tap][o]
// B fragments in per-lane order: [((l*4+kt)*8+nt)*2+term]*32 + lane
__device__ __align__(16) uint2  g_wfrag[4 * 4 * 8 * 2 * 32];
// bias fragments: [(l*8+nt)*32 + lane]
__device__ __align__(8)  float2 g_bfrag[4 * 8 * 32];

// ---------------------------------------------------------------------------
// Prep: conv0 transpose + per-lane B/bias fragment tables (bf16 hi/lo split)
// ---------------------------------------------------------------------------
__global__ void kprep(const float* __restrict__ w0,
                      const float* __restrict__ w1, const float* __restrict__ w2,
                      const float* __restrict__ w3, const float* __restrict__ w4,
                      const float* __restrict__ b1, const float* __restrict__ b2,
                      const float* __restrict__ b3, const float* __restrict__ b4)
{
    const int i = blockIdx.x * 256 + threadIdx.x;
    if (i < NTAP0 * HID) {
        const int tap = i >> 6;
        const int o   = i & 63;
        g_w0t[tap * HID + o] = w0[o * NTAP0 + tap];
    }
    if (i < 8192) {   // B fragments
        const int lane = i & 31;
        const int term = (i >> 5) & 1;
        const int nt   = (i >> 6) & 7;
        const int kt   = (i >> 9) & 3;
        const int l    = i >> 11;
        const float* w = (l == 0) ? w1 : (l == 1) ? w2 : (l == 2) ? w3 : w4;
        const int n  = 8 * nt + (lane >> 2);
        const int k0 = 16 * kt + 2 * (lane & 3);
        float e[4];
        const int ks[4] = { k0, k0 + 1, k0 + 8, k0 + 9 };
#pragma unroll
        for (int q = 0; q < 4; q++) {
            const float v = w[n * HID + ks[q]];
            const float hv = __bfloat162float(__float2bfloat16(v));
            e[q] = (term == 0) ? hv : (v - hv);
        }
        uint2 r;
        r.x = bf16x2_rn(e[0], e[1]);   // b0 low, b1 high
        r.y = bf16x2_rn(e[2], e[3]);   // b2 low, b3 high
        g_wfrag[i] = r;
    }
    if (i < 1024) {   // bias fragments
        const int lane = i & 31;
        const int nt   = (i >> 5) & 7;
        const int l    = i >> 8;
        const float* bb = (l == 0) ? b1 : (l == 1) ? b2 : (l == 2) ? b3 : b4;
        const int c = 8 * nt + 2 * (lane & 3);
        g_bfrag[i] = make_float2(bb[c], bb[c + 1]);
    }
}

// ---------------------------------------------------------------------------
// Kernel A: conv0 (fp32 FFMA2) + 4x (1x1 64->64) via register-chained
// mma.m16n8k16 bf16 3-term split. Block = 256 thr = 128-px strip; warp w owns
// px rows 16w..16w+15; layers chain in registers (D-frag == A-frag layout).
// ---------------------------------------------------------------------------
#define H0LD 70   /* staging tile ld (floats); stride 280 B rotates banks */

__global__ void __launch_bounds__(256, 2) knet_reg(
    const float* __restrict__ input, const float* __restrict__ ft,
    const float* __restrict__ b0)
{
    __shared__ float h0[128 * H0LD];   // 35840 B staging tile

    const int t  = threadIdx.x;
    const int xs = blockIdx.x;   // 0/1 x-half
    const int y  = blockIdx.y;
    const int b  = blockIdx.z;
    const int xbase = xs * 128;

    // ---- conv0: thread = 8 channels (jg) x 4 pixels (pg + 32m) -> h0 ----
    {
        const int jg = t >> 5;
        const int pg = t & 31;
        ull acc[4][4];
        {
            const float* bp = b0 + jg * 8;
#pragma unroll
            for (int p = 0; p < 4; p++) {
                const ull bv = pack2(bp[2 * p], bp[2 * p + 1]);
#pragma unroll
                for (int m = 0; m < 4; m++) acc[p][m] = bv;
            }
        }
        const float* zb = input + (size_t)b * 8 * HW;
        const float* fb = ft    + (size_t)b * FT_C * HW;
#pragma unroll
        for (int ci = 0; ci < CIN0; ci++) {
            const float* src = (ci < C_NN) ? (zb + ci * HW) : (fb + (ci - C_NN) * HW);
#pragma unroll
            for (int ky = 0; ky < 3; ky++) {
                const int yy = y + ky - 1;
                const bool yv = (unsigned)yy < HH;
                const float* rowp = src + yy * WW;
                float v[4][3];
#pragma unroll
                for (int m = 0; m < 4; m++) {
                    const int x = xbase + pg + 32 * m;
                    v[m][0] = (yv && x > 0)      ? __ldg(rowp + x - 1) : 0.f;
                    v[m][1] = yv                 ? __ldg(rowp + x)     : 0.f;
                    v[m][2] = (yv && x < WW - 1) ? __ldg(rowp + x + 1) : 0.f;
                }
#pragma unroll
                for (int kx = 0; kx < 3; kx++) {
                    const ulonglong2* wr = (const ulonglong2*)
                        (g_w0t + (ci * 9 + ky * 3 + kx) * HID + jg * 8);
                    ulonglong2 w0v = wr[0], w1v = wr[1];
#pragma unroll
                    for (int m = 0; m < 4; m++) {
                        const ull td = pack2(v[m][kx], v[m][kx]);
                        acc[0][m] = ffma2(w0v.x, td, acc[0][m]);
                        acc[1][m] = ffma2(w0v.y, td, acc[1][m]);
                        acc[2][m] = ffma2(w1v.x, td, acc[2][m]);
                        acc[3][m] = ffma2(w1v.y, td, acc[3][m]);
                    }
                }
            }
        }
        // relu + store fp32 to staging tile [px][ch]
#pragma unroll
        for (int m = 0; m < 4; m++) {
            const int px = pg + 32 * m;
#pragma unroll
            for (int p = 0; p < 4; p++) {
                const int ch = jg * 8 + 2 * p;
                float f0, f1; unpack2(acc[p][m], f0, f1);
                h0[px * H0LD + ch]     = fmaxf(f0, 0.f);
                h0[px * H0LD + ch + 1] = fmaxf(f1, 0.f);
            }
        }
    }
    __syncthreads();

    // ---- register-chained MMA layers ----
    const int w    = t >> 5;
    const int lane = t & 31;
    const int gp   = lane >> 2;     // groupID (row within tile)
    const int tg   = lane & 3;      // thread-in-group (col pair)
    const int r0   = 16 * w + gp;
    const int r1   = r0 + 8;

    // Build initial A (hi/lo) from staging tile
    uint32_t ahi[4][4], alo[4][4];
#pragma unroll
    for (int kt = 0; kt < 4; kt++) {
        const int c0 = 16 * kt + 2 * tg;
        const int c8 = c0 + 8;
        float2 e00 = *(const float2*)&h0[r0 * H0LD + c0];
        float2 e10 = *(const float2*)&h0[r1 * H0LD + c0];
        float2 e01 = *(const float2*)&h0[r0 * H0LD + c8];
        float2 e11 = *(const float2*)&h0[r1 * H0LD + c8];
        split_pair(ahi[kt][0], alo[kt][0], e00.x, e00.y);   // a0,a1
        split_pair(ahi[kt][1], alo[kt][1], e10.x, e10.y);   // a2,a3
        split_pair(ahi[kt][2], alo[kt][2], e01.x, e01.y);   // a4,a5
        split_pair(ahi[kt][3], alo[kt][3], e11.x, e11.y);   // a6,a7
    }

    float d[8][4];
#pragma unroll 1
    for (int l = 0; l < 4; l++) {
        // D init from bias fragments (bias broadcast over rows)
#pragma unroll
        for (int nt = 0; nt < 8; nt++) {
            float2 bb = g_bfrag[(l * 8 + nt) * 32 + lane];
            d[nt][0] = bb.x; d[nt][1] = bb.y;
            d[nt][2] = bb.x; d[nt][3] = bb.y;
        }
        // 3-term split MMA: Ahi*Bhi + Alo*Bhi + Ahi*Blo
#pragma unroll
        for (int kt = 0; kt < 4; kt++) {
#pragma unroll
            for (int nt = 0; nt < 8; nt++) {
                const uint2* wf = g_wfrag + ((((l * 4 + kt) * 8 + nt) * 2) * 32) + lane;
                uint2 Bh = wf[0];
                uint2 Bl = wf[32];
                MMA_16816(d[nt], ahi[kt], Bh.x, Bh.y);
                MMA_16816(d[nt], alo[kt], Bh.x, Bh.y);
                MMA_16816(d[nt], ahi[kt], Bl.x, Bl.y);
            }
        }
        if (l < 3) {
            // relu + re-split D -> next layer's A (pure per-lane, no smem)
#pragma unroll
            for (int j = 0; j < 4; j++) {
                const float x0 = fmaxf(d[2 * j][0], 0.f);
                const float x1 = fmaxf(d[2 * j][1], 0.f);
                const float x2 = fmaxf(d[2 * j][2], 0.f);
                const float x3 = fmaxf(d[2 * j][3], 0.f);
                const float y0 = fmaxf(d[2 * j + 1][0], 0.f);
                const float y1 = fmaxf(d[2 * j + 1][1], 0.f);
                const float y2 = fmaxf(d[2 * j + 1][2], 0.f);
                const float y3 = fmaxf(d[2 * j + 1][3], 0.f);
                split_pair(ahi[j][0], alo[j][0], x0, x1);
                split_pair(ahi[j][1], alo[j][1], x2, x3);
                split_pair(ahi[j][2], alo[j][2], y0, y1);
                split_pair(ahi[j][3], alo[j][3], y2, y3);
            }
        }
    }

    // final relu -> staging tile (warp-disjoint rows, no sync needed yet)
#pragma unroll
    for (int nt = 0; nt < 8; nt++) {
        const int c = 8 * nt + 2 * tg;
        *(float2*)&h0[r0 * H0LD + c] =
            make_float2(fmaxf(d[nt][0], 0.f), fmaxf(d[nt][1], 0.f));
        *(float2*)&h0[r1 * H0LD + c] =
            make_float2(fmaxf(d[nt][2], 0.f), fmaxf(d[nt][3], 0.f));
    }
    __syncthreads();

    // coalesced write to g_hidden
    const size_t gb = ((size_t)b * HID) * HW + (size_t)y * WW + xbase;
#pragma unroll
    for (int it = 0; it < 32; it++) {
        const int idx = it * 256 + t;
        const int ch  = idx >> 7;
        const int px  = idx & 127;
        g_hidden[gb + (size_t)ch * HW + px] = h0[px * H0LD + ch];
    }
}

// ---------------------------------------------------------------------------
// Kernel B: convz(3x3, 64->16) + spline (round-5 passing version, unchanged)
// ---------------------------------------------------------------------------
__global__ void __launch_bounds__(256, 2) kspline(
    const float* __restrict__ input,
    const float* __restrict__ wz, const float* __restrict__ bz,
    const float* __restrict__ logs,
    float* __restrict__ out)
{
    __shared__ __align__(16) float swz[HID * 9 * OUTC];
    __shared__ float sbz[OUTC];
    __shared__ float sscale[OUTC];
    __shared__ float sred[8];

    const int t = threadIdx.x;
    for (int i = t; i < HID * 9 * OUTC; i += 256) {
        const int o  = i & 15;
        const int ct = i >> 4;
        swz[i] = wz[o * (HID * 9) + ct];
    }
    if (t < OUTC) {
        sbz[t]    = bz[t];
        sscale[t] = expf(3.f * logs[t]);
    }
    __syncthreads();

    const int warp = t >> 5;
    const int lane = t & 31;
    const int b  = blockIdx.z;
    const int y  = blockIdx.y * 4 + (warp >> 1);
    const int xh = warp & 1;
    const int x0 = xh * 128 + lane * 4;

    ull accp[4][8];
#pragma unroll
    for (int j = 0; j < 4; j++)
#pragma unroll
        for (int p = 0; p < 8; p++) accp[j][p] = 0ull;

    const float* hb = g_hidden + (size_t)b * HID * HW;

#pragma unroll 1
    for (int c = 0; c < HID; c++) {
        const float* hp = hb + (size_t)c * HW;
        float e[3][6];
#pragma unroll
        for (int r = 0; r < 3; r++) {
            const int yy = y + r - 1;
            const bool yv = (unsigned)yy < HH;
            float4 v;
            if (yv) v = *(const float4*)(hp + yy * WW + x0);
            else    v = make_float4(0.f, 0.f, 0.f, 0.f);
            float lft = __shfl_up_sync(0xffffffffu, v.w, 1);
            float rgt = __shfl_down_sync(0xffffffffu, v.x, 1);
            if (lane == 0)  lft = (yv && x0 > 0)      ? __ldg(hp + yy * WW + x0 - 1) : 0.f;
            if (lane == 31) rgt = (yv && x0 + 4 < WW) ? __ldg(hp + yy * WW + x0 + 4) : 0.f;
            e[r][0] = lft; e[r][1] = v.x; e[r][2] = v.y;
            e[r][3] = v.z; e[r][4] = v.w; e[r][5] = rgt;
        }
#pragma unroll
        for (int r = 0; r < 3; r++) {
#pragma unroll
            for (int kx = 0; kx < 3; kx++) {
                const int tt = r * 3 + kx;
                const ulonglong2* wt =
                    (const ulonglong2*)(swz + (c * 9 + tt) * OUTC);
                ulonglong2 wv0 = wt[0], wv1 = wt[1];
                ulonglong2 wv2 = wt[2], wv3 = wt[3];
#pragma unroll
                for (int j = 0; j < 4; j++) {
                    const float ev = e[r][j + kx];
                    const ull dd = pack2(ev, ev);
                    accp[j][0] = ffma2(wv0.x, dd, accp[j][0]);
                    accp[j][1] = ffma2(wv0.y, dd, accp[j][1]);
                    accp[j][2] = ffma2(wv1.x, dd, accp[j][2]);
                    accp[j][3] = ffma2(wv1.y, dd, accp[j][3]);
                    accp[j][4] = ffma2(wv2.x, dd, accp[j][4]);
                    accp[j][5] = ffma2(wv2.y, dd, accp[j][5]);
                    accp[j][6] = ffma2(wv3.x, dd, accp[j][6]);
                    accp[j][7] = ffma2(wv3.y, dd, accp[j][7]);
                }
            }
        }
    }

    const float* xin = input + (size_t)b * 8 * HW + (size_t)y * WW + x0;
    float*       oo  = out   + (size_t)b * 8 * HW + (size_t)y * WW + x0;
    float ladsum = 0.f;

#pragma unroll
    for (int co = 0; co < C_CO; co++) {
        *(float4*)(oo + (size_t)co * HW) = *(const float4*)(xin + (size_t)co * HW);

        float4 x2v = *(const float4*)(xin + (size_t)(4 + co) * HW);
        const float x2a[4] = { x2v.x, x2v.y, x2v.z, x2v.w };
        float rs[4];
#pragma unroll
        for (int j = 0; j < 4; j++) {
            float rw, rh, rd, sh;
            unpack2(accp[j][2 * co],     rw, rh);
            unpack2(accp[j][2 * co + 1], rd, sh);
            rw = (rw + sbz[co * 4 + 0]) * sscale[co * 4 + 0];
            rh = (rh + sbz[co * 4 + 1]) * sscale[co * 4 + 1];
            rd = (rd + sbz[co * 4 + 2]) * sscale[co * 4 + 2];
            sh = (sh + sbz[co * 4 + 3]) * sscale[co * 4 + 3];

            const float x2 = x2a[j];
            const bool inside = (x2 > -0.5f) && (x2 < 0.5f);
            const float xs2 = inside ? x2 : 0.f;

            const float width = 1.f / (1.f + expf(-rw)) * 0.998f + 0.001f;
            const float hh2   = 1.f / (1.f + expf(-rh)) * 0.998f + 0.001f;
            const float dd    = expf(rd) * 0.999f + 0.001f;

            const float cw1 = width - 0.5f;
            const float ch1 = hh2   - 0.5f;
            const bool bin1 = xs2 >= cw1;

            const float in_cw = bin1 ? cw1 : -0.5f;
            const float in_w  = bin1 ? (0.5f - cw1) : (cw1 + 0.5f);
            const float in_ch = bin1 ? ch1 : -0.5f;
            const float in_h  = bin1 ? (0.5f - ch1) : (ch1 + 0.5f);
            const float d0    = bin1 ? dd : 1.f;
            const float d1    = bin1 ? 1.f : dd;

            const float delta = in_h / in_w;
            const float theta = (xs2 - in_cw) / in_w;
            const float omt   = 1.f - theta;
            const float t1mt  = theta * omt;
            const float denom = delta + (d0 + d1 - 2.f * delta) * t1mt;
            float outv = in_ch + in_h * (delta * theta * theta + d0 * t1mt) / denom;
            const float dnum = delta * delta *
                (d1 * theta * theta + 2.f * delta * t1mt + d0 * omt * omt);
            const float lad  = logf(dnum) - 2.f * logf(denom);
            outv = fminf(fmaxf(outv, -0.5f), 0.5f);

            rs[j] = (inside ? outv : x2) + sh;
            ladsum += inside ? lad : 0.f;
        }
        *(float4*)(oo + (size_t)(4 + co) * HW) = make_float4(rs[0], rs[1], rs[2], rs[3]);
    }

#pragma unroll
    for (int off = 16; off; off >>= 1)
        ladsum += __shfl_down_sync(0xffffffffu, ladsum, off);
    if (lane == 0) sred[warp] = ladsum;
    __syncthreads();
    if (t < 8) {
        float v = sred[t];
#pragma unroll
        for (int off = 4; off; off >>= 1)
            v += __shfl_down_sync(0xffu, v, off);
        if (t == 0) atomicAdd(out + (size_t)BATCH * 8 * HW + b, v);
    }
}

// Seed the logdet outputs from the input logdet (d_out is poisoned).
__global__ void kinit(const float* __restrict__ logdet, float* __restrict__ out)
{
    const int t = threadIdx.x;
    if (t < BATCH) out[(size_t)BATCH * 8 * HW + t] = logdet[t];
}

// ---------------------------------------------------------------------------
extern "C" void kernel_launch(void* const* d_in, const int* in_sizes, int n_in,
                              void* d_out, int out_size)
{
    const float* input  = (const float*)d_in[0];
    const float* logdet = (const float*)d_in[1];
    const float* ft     = (const float*)d_in[2];
    const float* w0     = (const float*)d_in[3];
    const float* b0     = (const float*)d_in[4];
    const float* w1     = (const float*)d_in[5];
    const float* b1     = (const float*)d_in[6];
    const float* w2     = (const float*)d_in[7];
    const float* b2     = (const float*)d_in[8];
    const float* w3     = (const float*)d_in[9];
    const float* b3     = (const float*)d_in[10];
    const float* w4     = (const float*)d_in[11];
    const float* b4     = (const float*)d_in[12];
    const float* wz     = (const float*)d_in[13];
    const float* bz     = (const float*)d_in[14];
    const float* logs   = (const float*)d_in[15];
    float* out = (float*)d_out;

    kinit<<<1, 32>>>(logdet, out);
    kprep<<<32, 256>>>(w0, w1, w2, w3, w4, b1, b2, b3, b4);

    dim3 gA(2, 256, 16);
    knet_reg<<<gA, 256>>>(input, ft, b0);

    dim3 gB(1, 64, 16);
    kspline<<<gB, 256>>>(input, wz, bz, logs, out);
}